// round 10
// baseline (speedup 1.0000x reference)
#include <cuda_runtime.h>
#include <cuda_bf16.h>
#include <cstdint>

// Problem constants (fixed by the dataset)
#define MAXN 100000
#define MAXE 1600000
#define HDIM 128
#define NSCAN_BLOCKS ((MAXN + 1023) / 1024)

// ---------------- scratch (device globals; no runtime allocation) ----------
__device__ int   g_cnt[MAXN];
__device__ int   g_rowptr[MAXN + 1];
__device__ int2  g_edge[MAXE];          // packed (src, nrm-as-int) per edge
__device__ int   g_bsum[NSCAN_BLOCKS + 1];
__device__ __nv_bfloat16 g_hb[(size_t)MAXN * HDIM];  // post-GEMM features (bf16)
__device__ __nv_bfloat16 g_xb[(size_t)MAXN * HDIM];  // aggregate out / GEMM in (bf16)
__device__ __nv_bfloat16 g_Wth[3 * HDIM * HDIM];     // W^T hi  [n][k] bf16
__device__ __nv_bfloat16 g_Wtl[3 * HDIM * HDIM];     // W^T lo  [n][k] bf16

// ---------------- helpers ----------------------------------------------------
__device__ __forceinline__ uint32_t smem_to_u32(const void* p) {
    uint32_t a;
    asm("{ .reg .u64 t; cvta.to.shared.u64 t, %1; cvt.u32.u64 %0, t; }"
        : "=r"(a) : "l"(p));
    return a;
}

__device__ __forceinline__ void ldsm_x4(uint32_t addr, uint32_t& r0, uint32_t& r1,
                                        uint32_t& r2, uint32_t& r3) {
    asm volatile("ldmatrix.sync.aligned.m8n8.x4.shared.b16 {%0,%1,%2,%3}, [%4];"
                 : "=r"(r0), "=r"(r1), "=r"(r2), "=r"(r3) : "r"(addr));
}

__device__ __forceinline__ void mma_bf16(float* c, uint32_t a0, uint32_t a1,
                                         uint32_t a2, uint32_t a3,
                                         uint32_t b0, uint32_t b1) {
    asm volatile(
        "mma.sync.aligned.m16n8k16.row.col.f32.bf16.bf16.f32 "
        "{%0,%1,%2,%3}, {%4,%5,%6,%7}, {%8,%9}, {%0,%1,%2,%3};"
        : "+f"(c[0]), "+f"(c[1]), "+f"(c[2]), "+f"(c[3])
        : "r"(a0), "r"(a1), "r"(a2), "r"(a3), "r"(b0), "r"(b1));
}

__device__ __forceinline__ void split_bf16(float v, __nv_bfloat16& hi, __nv_bfloat16& lo) {
    hi = __float2bfloat16_rn(v);
    lo = __float2bfloat16_rn(v - __bfloat162float(hi));
}

__device__ __forceinline__ void acc8(float* a, uint4 u, float w) {
    float2 t;
    t = __bfloat1622float2(*(__nv_bfloat162*)&u.x); a[0] += t.x * w; a[1] += t.y * w;
    t = __bfloat1622float2(*(__nv_bfloat162*)&u.y); a[2] += t.x * w; a[3] += t.y * w;
    t = __bfloat1622float2(*(__nv_bfloat162*)&u.z); a[4] += t.x * w; a[5] += t.y * w;
    t = __bfloat1622float2(*(__nv_bfloat162*)&u.w); a[6] += t.x * w; a[7] += t.y * w;
}

// ---------------- CSR build -------------------------------------------------
__global__ void k_init(int n) {
    int i = blockIdx.x * blockDim.x + threadIdx.x;
    if (i < n) g_cnt[i] = 0;
}

__global__ void k_count(const int* __restrict__ dst, int e) {
    int i = blockIdx.x * blockDim.x + threadIdx.x;
    if (i < e) atomicAdd(&g_cnt[dst[i]], 1);
}

__global__ void k_scan1(int n) {
    int i = blockIdx.x * 1024 + threadIdx.x;
    int v = (i < n) ? g_cnt[i] : 0;
    int lane = threadIdx.x & 31, wid = threadIdx.x >> 5;
    int x = v;
    #pragma unroll
    for (int o = 1; o < 32; o <<= 1) {
        int y = __shfl_up_sync(0xFFFFFFFFu, x, o);
        if (lane >= o) x += y;
    }
    __shared__ int ws[32];
    if (lane == 31) ws[wid] = x;
    __syncthreads();
    if (wid == 0) {
        int w = ws[lane];
        #pragma unroll
        for (int o = 1; o < 32; o <<= 1) {
            int y = __shfl_up_sync(0xFFFFFFFFu, w, o);
            if (lane >= o) w += y;
        }
        ws[lane] = w;
    }
    __syncthreads();
    int prefix = (wid > 0) ? ws[wid - 1] : 0;
    int incl = x + prefix;
    if (i < n) g_rowptr[i] = incl - v;
    if (threadIdx.x == 1023) g_bsum[blockIdx.x] = incl;
}

// parallel 128-thread exclusive scan of block sums (nb <= 128)
__global__ void k_scan2(int nb) {
    int t = threadIdx.x;
    int lane = t & 31, wid = t >> 5;
    int v = (t < nb) ? g_bsum[t] : 0;
    int x = v;
    #pragma unroll
    for (int o = 1; o < 32; o <<= 1) {
        int y = __shfl_up_sync(0xFFFFFFFFu, x, o);
        if (lane >= o) x += y;
    }
    __shared__ int ws[4];
    if (lane == 31) ws[wid] = x;
    __syncthreads();
    int prefix = 0;
    #pragma unroll
    for (int w = 0; w < 4; w++) prefix += (w < wid) ? ws[w] : 0;
    if (t < nb) g_bsum[t] = x + prefix - v;   // exclusive
}

__global__ void k_scan3(int n, int e) {
    int i = blockIdx.x * blockDim.x + threadIdx.x;
    if (i < n) g_rowptr[i] += g_bsum[i >> 10];
    if (i == 0) g_rowptr[n] = e;
}

// countdown-cursor fill; degree from rowptr diffs (+1 self-loop)
__global__ void k_fill(const int* __restrict__ src, const int* __restrict__ dst, int e) {
    int i = blockIdx.x * blockDim.x + threadIdx.x;
    if (i >= e) return;
    int d = dst[i], s = src[i];
    int rpd1 = g_rowptr[d + 1];
    int c = atomicAdd(&g_cnt[d], -1);
    int p = rpd1 - c;
    float degd = (float)(rpd1 - g_rowptr[d] + 1);
    float degs = (float)(g_rowptr[s + 1] - g_rowptr[s] + 1);
    float nrm = rsqrtf(degs * degd);
    g_edge[p] = make_int2(s, __float_as_int(nrm));
}

// ---------------- prep: weights transposed + split --------------------------
__global__ void k_wconv(const float* __restrict__ W0, const float* __restrict__ W1,
                        const float* __restrict__ W2) {
    int i = blockIdx.x * blockDim.x + threadIdx.x;
    if (i >= 3 * HDIM * HDIM) return;
    int l = i / (HDIM * HDIM);
    int r = i % (HDIM * HDIM);
    int nn = r / HDIM, kk = r % HDIM;
    const float* W = (l == 0) ? W0 : (l == 1) ? W1 : W2;
    float v = W[kk * HDIM + nn];
    __nv_bfloat16 hi, lo;
    split_bf16(v, hi, lo);
    g_Wth[l * HDIM * HDIM + nn * HDIM + kk] = hi;
    g_Wtl[l * HDIM * HDIM + nn * HDIM + kk] = lo;
}

// ---------------- GEMM: Hb = A @ W + b via mma.sync -------------------------
// A from fp32 X0 (layer 0, converted in-register) or bf16 g_xb (layers 1,2).
#define PADB 272
#define SM_A  0
#define SM_BH (128 * PADB)
#define SM_BL (2 * 128 * PADB)
#define SM_TOT (3 * 128 * PADB)

__global__ __launch_bounds__(256, 2) void k_gemm_mma(
    const float* __restrict__ X0,
    const __nv_bfloat16* __restrict__ Wh,
    const __nv_bfloat16* __restrict__ Wl,
    const float* __restrict__ bias,
    int n)
{
    extern __shared__ __align__(16) char smem[];
    uint32_t sb = smem_to_u32(smem);
    int tid = threadIdx.x;
    int lane = tid & 31, wid = tid >> 5;
    int wr = wid & 3;
    int wc = wid >> 2;
    int blockRow = blockIdx.x * 128;

    // B fill (always) + A fill (two sources)
    #pragma unroll
    for (int i = 0; i < 8; i++) {
        int gi = tid + i * 256;
        int r = gi >> 4, c16 = gi & 15;
        *(uint4*)(smem + SM_BH + r * PADB + c16 * 16) =
            *(const uint4*)&Wh[(size_t)r * HDIM + c16 * 8];
        *(uint4*)(smem + SM_BL + r * PADB + c16 * 16) =
            *(const uint4*)&Wl[(size_t)r * HDIM + c16 * 8];
    }
    if (X0 != nullptr) {
        #pragma unroll
        for (int i = 0; i < 8; i++) {
            int gi = tid + i * 256;
            int r = gi >> 4, c8 = (gi & 15) << 3;
            int row = blockRow + r;
            uint4 va = make_uint4(0, 0, 0, 0);
            if (row < n) {
                float4 v0 = *(const float4*)&X0[(size_t)row * HDIM + c8];
                float4 v1 = *(const float4*)&X0[(size_t)row * HDIM + c8 + 4];
                __nv_bfloat162 a, b, c, d;
                a.x = __float2bfloat16_rn(v0.x); a.y = __float2bfloat16_rn(v0.y);
                b.x = __float2bfloat16_rn(v0.z); b.y = __float2bfloat16_rn(v0.w);
                c.x = __float2bfloat16_rn(v1.x); c.y = __float2bfloat16_rn(v1.y);
                d.x = __float2bfloat16_rn(v1.z); d.y = __float2bfloat16_rn(v1.w);
                va.x = *(uint32_t*)&a; va.y = *(uint32_t*)&b;
                va.z = *(uint32_t*)&c; va.w = *(uint32_t*)&d;
            }
            *(uint4*)(smem + SM_A + r * PADB + c8 * 2) = va;
        }
    } else {
        #pragma unroll
        for (int i = 0; i < 8; i++) {
            int gi = tid + i * 256;
            int r = gi >> 4, c16 = gi & 15;
            int row = blockRow + r;
            uint4 va = make_uint4(0, 0, 0, 0);
            if (row < n) va = *(const uint4*)&g_xb[(size_t)row * HDIM + c16 * 8];
            *(uint4*)(smem + SM_A + r * PADB + c16 * 16) = va;
        }
    }
    __syncthreads();

    float c[2][8][4];
    #pragma unroll
    for (int mt = 0; mt < 2; mt++)
        #pragma unroll
        for (int nt = 0; nt < 8; nt++)
            #pragma unroll
            for (int j = 0; j < 4; j++) c[mt][nt][j] = 0.0f;

    int q = lane >> 3, rl = lane & 7;
    int rowA = wr * 32 + (q & 1) * 8 + rl;
    int colA = (q >> 1) * 16;
    int rowB = wc * 64 + (q >> 1) * 8 + rl;
    int colB = (q & 1) * 16;

    #pragma unroll
    for (int ks = 0; ks < 8; ks++) {
        uint32_t a[2][4];
        #pragma unroll
        for (int mt = 0; mt < 2; mt++)
            ldsm_x4(sb + SM_A + (rowA + mt * 16) * PADB + ks * 32 + colA,
                    a[mt][0], a[mt][1], a[mt][2], a[mt][3]);

        #pragma unroll
        for (int pass = 0; pass < 2; pass++) {
            uint32_t base = pass ? SM_BL : SM_BH;
            uint32_t b[8][2];
            #pragma unroll
            for (int pr = 0; pr < 4; pr++)
                ldsm_x4(sb + base + (rowB + pr * 16) * PADB + ks * 32 + colB,
                        b[2 * pr][0], b[2 * pr][1], b[2 * pr + 1][0], b[2 * pr + 1][1]);
            #pragma unroll
            for (int mt = 0; mt < 2; mt++)
                #pragma unroll
                for (int nt = 0; nt < 8; nt++)
                    mma_bf16(c[mt][nt], a[mt][0], a[mt][1], a[mt][2], a[mt][3],
                             b[nt][0], b[nt][1]);
        }
    }

    int g = lane >> 2, t = lane & 3;
    #pragma unroll
    for (int nt = 0; nt < 8; nt++) {
        int col = wc * 64 + nt * 8 + 2 * t;
        float2 bv = *(const float2*)&bias[col];
        #pragma unroll
        for (int mt = 0; mt < 2; mt++) {
            int row0 = blockRow + wr * 32 + mt * 16 + g;
            if (row0 < n) {
                __nv_bfloat162 p;
                p.x = __float2bfloat16_rn(c[mt][nt][0] + bv.x);
                p.y = __float2bfloat16_rn(c[mt][nt][1] + bv.y);
                *(__nv_bfloat162*)&g_hb[(size_t)row0 * HDIM + col] = p;
            }
            if (row0 + 8 < n) {
                __nv_bfloat162 p;
                p.x = __float2bfloat16_rn(c[mt][nt][2] + bv.x);
                p.y = __float2bfloat16_rn(c[mt][nt][3] + bv.y);
                *(__nv_bfloat162*)&g_hb[(size_t)(row0 + 8) * HDIM + col] = p;
            }
        }
    }
}

// ---------------- aggregation: half-warp per node, packed edges, 4-wide -----
__global__ __launch_bounds__(256) void k_aggregate(int n) {
    int node = (blockIdx.x * blockDim.x + threadIdx.x) >> 4;
    int hl = threadIdx.x & 15;
    if (node >= n) return;
    int cbase = hl * 8;

    int beg = g_rowptr[node], end = g_rowptr[node + 1];
    float invd = 1.0f / (float)(end - beg + 1);

    float a[8];
    {
        uint4 us = *(const uint4*)&g_hb[(size_t)node * HDIM + cbase];
        float2 t;
        t = __bfloat1622float2(*(__nv_bfloat162*)&us.x); a[0] = t.x * invd; a[1] = t.y * invd;
        t = __bfloat1622float2(*(__nv_bfloat162*)&us.y); a[2] = t.x * invd; a[3] = t.y * invd;
        t = __bfloat1622float2(*(__nv_bfloat162*)&us.z); a[4] = t.x * invd; a[5] = t.y * invd;
        t = __bfloat1622float2(*(__nv_bfloat162*)&us.w); a[6] = t.x * invd; a[7] = t.y * invd;
    }

    int p = beg;
    for (; p + 3 < end; p += 4) {
        int2 e0 = g_edge[p],     e1 = g_edge[p + 1];
        int2 e2 = g_edge[p + 2], e3 = g_edge[p + 3];
        uint4 u0 = *(const uint4*)&g_hb[(size_t)e0.x * HDIM + cbase];
        uint4 u1 = *(const uint4*)&g_hb[(size_t)e1.x * HDIM + cbase];
        uint4 u2 = *(const uint4*)&g_hb[(size_t)e2.x * HDIM + cbase];
        uint4 u3 = *(const uint4*)&g_hb[(size_t)e3.x * HDIM + cbase];
        acc8(a, u0, __int_as_float(e0.y));
        acc8(a, u1, __int_as_float(e1.y));
        acc8(a, u2, __int_as_float(e2.y));
        acc8(a, u3, __int_as_float(e3.y));
    }
    for (; p < end; p++) {
        int2 e0 = g_edge[p];
        uint4 u = *(const uint4*)&g_hb[(size_t)e0.x * HDIM + cbase];
        acc8(a, u, __int_as_float(e0.y));
    }

    #pragma unroll
    for (int j = 0; j < 8; j++) a[j] = fmaxf(a[j], 0.0f);

    __nv_bfloat162 p0, p1, p2, p3;
    p0.x = __float2bfloat16_rn(a[0]); p0.y = __float2bfloat16_rn(a[1]);
    p1.x = __float2bfloat16_rn(a[2]); p1.y = __float2bfloat16_rn(a[3]);
    p2.x = __float2bfloat16_rn(a[4]); p2.y = __float2bfloat16_rn(a[5]);
    p3.x = __float2bfloat16_rn(a[6]); p3.y = __float2bfloat16_rn(a[7]);
    uint4 pk;
    pk.x = *(uint32_t*)&p0; pk.y = *(uint32_t*)&p1;
    pk.z = *(uint32_t*)&p2; pk.w = *(uint32_t*)&p3;
    *(uint4*)&g_xb[(size_t)node * HDIM + cbase] = pk;
}

// ---------------- segment-mean pool (bf16 input) + 2-layer MLP head ---------
__device__ __forceinline__ int lbound(const int* __restrict__ a, int n, int key) {
    int lo = 0, hi = n;
    while (lo < hi) { int m = (lo + hi) >> 1; if (a[m] < key) lo = m + 1; else hi = m; }
    return lo;
}

__global__ __launch_bounds__(128) void k_pool_mlp(const int* __restrict__ batch, int n,
                                                  const float* __restrict__ Wp1,
                                                  const float* __restrict__ bp1,
                                                  const float* __restrict__ Wp2,
                                                  const float* __restrict__ bp2,
                                                  float* __restrict__ out) {
    int g = blockIdx.x;
    int t = threadIdx.x;
    int beg = lbound(batch, n, g);
    int end = lbound(batch, n, g + 1);
    float s = 0.0f;
    for (int r = beg; r < end; r++)
        s += __bfloat162float(g_xb[(size_t)r * HDIM + t]);
    float cnt = (float)(end - beg);
    float inv = 1.0f / fmaxf(cnt, 1.0f);

    __shared__ float ps[HDIM];
    ps[t] = s * inv;
    __syncthreads();

    float hid = bp1[t];
    #pragma unroll
    for (int k = 0; k < HDIM; k++) hid += ps[k] * Wp1[k * HDIM + t];
    hid = fmaxf(hid, 0.0f);

    float term = hid * Wp2[t];
    #pragma unroll
    for (int o = 16; o > 0; o >>= 1) term += __shfl_down_sync(0xFFFFFFFFu, term, o);
    __shared__ float rs[4];
    int lane = t & 31, wid = t >> 5;
    if (lane == 0) rs[wid] = term;
    __syncthreads();
    if (t == 0) out[g] = rs[0] + rs[1] + rs[2] + rs[3] + bp2[0];
}

// ---------------- launch -----------------------------------------------------
extern "C" void kernel_launch(void* const* d_in, const int* in_sizes, int n_in,
                              void* d_out, int out_size) {
    const float* x     = (const float*)d_in[0];
    const int*   ei    = (const int*)d_in[1];
    const int*   batch = (const int*)d_in[2];
    const float* Ws[3] = {(const float*)d_in[3], (const float*)d_in[5], (const float*)d_in[7]};
    const float* bs[3] = {(const float*)d_in[4], (const float*)d_in[6], (const float*)d_in[8]};
    const float* Wp1 = (const float*)d_in[9];
    const float* bp1 = (const float*)d_in[10];
    const float* Wp2 = (const float*)d_in[11];
    const float* bp2 = (const float*)d_in[12];
    float* out = (float*)d_out;

    int n = in_sizes[0] / HDIM;
    int e = in_sizes[1] / 2;
    const int* src = ei;
    const int* dst = ei + e;

    int nb_n = (n + 255) / 256;
    int nb_e = (e + 255) / 256;
    int nscan = (n + 1023) / 1024;

    // one-time setup (host objects only; no device allocation)
    static cudaStream_t s1 = nullptr;
    static cudaEvent_t evFork = nullptr, evJoin = nullptr;
    if (s1 == nullptr) {
        cudaStreamCreateWithFlags(&s1, cudaStreamNonBlocking);
        cudaEventCreateWithFlags(&evFork, cudaEventDisableTiming);
        cudaEventCreateWithFlags(&evJoin, cudaEventDisableTiming);
        cudaFuncSetAttribute(k_gemm_mma, cudaFuncAttributeMaxDynamicSharedMemorySize, SM_TOT);
    }

    __nv_bfloat16* Wh0; cudaGetSymbolAddress((void**)&Wh0, g_Wth);
    __nv_bfloat16* Wl0; cudaGetSymbolAddress((void**)&Wl0, g_Wtl);

    int gemm_blocks = (n + 127) / 128;
    int agg_blocks = (n + 15) / 16;

    // ---- fork: CSR build on s1, concurrent with wconv + GEMM0 on stream 0 ----
    cudaEventRecord(evFork, 0);
    cudaStreamWaitEvent(s1, evFork, 0);

    // branch B (s1): CSR build
    k_init<<<nb_n, 256, 0, s1>>>(n);
    k_count<<<nb_e, 256, 0, s1>>>(dst, e);
    k_scan1<<<nscan, 1024, 0, s1>>>(n);
    k_scan2<<<1, 128, 0, s1>>>(nscan);
    k_scan3<<<nb_n, 256, 0, s1>>>(n, e);
    k_fill<<<nb_e, 256, 0, s1>>>(src, dst, e);
    cudaEventRecord(evJoin, s1);

    // branch A (stream 0): weight split + layer-0 GEMM (fp32 x converted in-fill)
    k_wconv<<<(3 * HDIM * HDIM + 255) / 256, 256>>>(Ws[0], Ws[1], Ws[2]);
    k_gemm_mma<<<gemm_blocks, 256, SM_TOT>>>(x, Wh0, Wl0, bs[0], n);

    // ---- join: aggregate needs both CSR and hb ----
    cudaStreamWaitEvent(0, evJoin, 0);

    k_aggregate<<<agg_blocks, 256>>>(n);
    k_gemm_mma<<<gemm_blocks, 256, SM_TOT>>>(nullptr, Wh0 + HDIM * HDIM,
                                             Wl0 + HDIM * HDIM, bs[1], n);
    k_aggregate<<<agg_blocks, 256>>>(n);
    k_gemm_mma<<<gemm_blocks, 256, SM_TOT>>>(nullptr, Wh0 + 2 * HDIM * HDIM,
                                             Wl0 + 2 * HDIM * HDIM, bs[2], n);
    k_aggregate<<<agg_blocks, 256>>>(n);

    // pool + MLP head
    k_pool_mlp<<<out_size, 128>>>(batch, n, Wp1, bp1, Wp2, bp2, out);
}

// round 11
// speedup vs baseline: 1.1358x; 1.1358x over previous
#include <cuda_runtime.h>
#include <cuda_bf16.h>
#include <cstdint>

// Problem constants (fixed by the dataset)
#define MAXN 100000
#define MAXE 1600000
#define HDIM 128
#define NSCAN_BLOCKS ((MAXN + 1023) / 1024)

// ---------------- scratch (device globals; no runtime allocation) ----------
__device__ int   g_cnt[MAXN];
__device__ int   g_rowptr[MAXN + 1];
__device__ int2  g_edge[MAXE];          // packed (src, nrm-as-int) per edge
__device__ int   g_bsum[NSCAN_BLOCKS + 1];
__device__ __nv_bfloat16 g_hb[(size_t)MAXN * HDIM];  // post-GEMM features (bf16)
__device__ __nv_bfloat16 g_xb[(size_t)MAXN * HDIM];  // aggregate out / GEMM in (bf16)
__device__ __nv_bfloat16 g_Wth[3 * HDIM * HDIM];     // W^T hi  [n][k] bf16
__device__ __nv_bfloat16 g_Wtl[3 * HDIM * HDIM];     // W^T lo  [n][k] bf16

// ---------------- helpers ----------------------------------------------------
__device__ __forceinline__ uint32_t smem_to_u32(const void* p) {
    uint32_t a;
    asm("{ .reg .u64 t; cvta.to.shared.u64 t, %1; cvt.u32.u64 %0, t; }"
        : "=r"(a) : "l"(p));
    return a;
}

__device__ __forceinline__ void ldsm_x4(uint32_t addr, uint32_t& r0, uint32_t& r1,
                                        uint32_t& r2, uint32_t& r3) {
    asm volatile("ldmatrix.sync.aligned.m8n8.x4.shared.b16 {%0,%1,%2,%3}, [%4];"
                 : "=r"(r0), "=r"(r1), "=r"(r2), "=r"(r3) : "r"(addr));
}

__device__ __forceinline__ void mma_bf16(float* c, uint32_t a0, uint32_t a1,
                                         uint32_t a2, uint32_t a3,
                                         uint32_t b0, uint32_t b1) {
    asm volatile(
        "mma.sync.aligned.m16n8k16.row.col.f32.bf16.bf16.f32 "
        "{%0,%1,%2,%3}, {%4,%5,%6,%7}, {%8,%9}, {%0,%1,%2,%3};"
        : "+f"(c[0]), "+f"(c[1]), "+f"(c[2]), "+f"(c[3])
        : "r"(a0), "r"(a1), "r"(a2), "r"(a3), "r"(b0), "r"(b1));
}

__device__ __forceinline__ void split_bf16(float v, __nv_bfloat16& hi, __nv_bfloat16& lo) {
    hi = __float2bfloat16_rn(v);
    lo = __float2bfloat16_rn(v - __bfloat162float(hi));
}

__device__ __forceinline__ void acc8(float* a, uint4 u, float w) {
    float2 t;
    t = __bfloat1622float2(*(__nv_bfloat162*)&u.x); a[0] += t.x * w; a[1] += t.y * w;
    t = __bfloat1622float2(*(__nv_bfloat162*)&u.y); a[2] += t.x * w; a[3] += t.y * w;
    t = __bfloat1622float2(*(__nv_bfloat162*)&u.z); a[4] += t.x * w; a[5] += t.y * w;
    t = __bfloat1622float2(*(__nv_bfloat162*)&u.w); a[6] += t.x * w; a[7] += t.y * w;
}

// ---------------- CSR build -------------------------------------------------
__global__ void k_init(int n) {
    int i = blockIdx.x * blockDim.x + threadIdx.x;
    if (i < n) g_cnt[i] = 0;
}

__global__ void k_count(const int* __restrict__ dst, int e) {
    int i = blockIdx.x * blockDim.x + threadIdx.x;
    if (i < e) atomicAdd(&g_cnt[dst[i]], 1);
}

__global__ void k_scan1(int n) {
    int i = blockIdx.x * 1024 + threadIdx.x;
    int v = (i < n) ? g_cnt[i] : 0;
    int lane = threadIdx.x & 31, wid = threadIdx.x >> 5;
    int x = v;
    #pragma unroll
    for (int o = 1; o < 32; o <<= 1) {
        int y = __shfl_up_sync(0xFFFFFFFFu, x, o);
        if (lane >= o) x += y;
    }
    __shared__ int ws[32];
    if (lane == 31) ws[wid] = x;
    __syncthreads();
    if (wid == 0) {
        int w = ws[lane];
        #pragma unroll
        for (int o = 1; o < 32; o <<= 1) {
            int y = __shfl_up_sync(0xFFFFFFFFu, w, o);
            if (lane >= o) w += y;
        }
        ws[lane] = w;
    }
    __syncthreads();
    int prefix = (wid > 0) ? ws[wid - 1] : 0;
    int incl = x + prefix;
    if (i < n) g_rowptr[i] = incl - v;
    if (threadIdx.x == 1023) g_bsum[blockIdx.x] = incl;
}

// parallel 128-thread exclusive scan of block sums (nb <= 128)
__global__ void k_scan2(int nb) {
    int t = threadIdx.x;
    int lane = t & 31, wid = t >> 5;
    int v = (t < nb) ? g_bsum[t] : 0;
    int x = v;
    #pragma unroll
    for (int o = 1; o < 32; o <<= 1) {
        int y = __shfl_up_sync(0xFFFFFFFFu, x, o);
        if (lane >= o) x += y;
    }
    __shared__ int ws[4];
    if (lane == 31) ws[wid] = x;
    __syncthreads();
    int prefix = 0;
    #pragma unroll
    for (int w = 0; w < 4; w++) prefix += (w < wid) ? ws[w] : 0;
    if (t < nb) g_bsum[t] = x + prefix - v;   // exclusive
}

__global__ void k_scan3(int n, int e) {
    int i = blockIdx.x * blockDim.x + threadIdx.x;
    if (i < n) g_rowptr[i] += g_bsum[i >> 10];
    if (i == 0) g_rowptr[n] = e;
}

// countdown-cursor fill; degree from rowptr diffs (+1 self-loop)
__global__ void k_fill(const int* __restrict__ src, const int* __restrict__ dst, int e) {
    int i = blockIdx.x * blockDim.x + threadIdx.x;
    if (i >= e) return;
    int d = dst[i], s = src[i];
    int rpd1 = g_rowptr[d + 1];
    int c = atomicAdd(&g_cnt[d], -1);
    int p = rpd1 - c;
    float degd = (float)(rpd1 - g_rowptr[d] + 1);
    float degs = (float)(g_rowptr[s + 1] - g_rowptr[s] + 1);
    float nrm = rsqrtf(degs * degd);
    g_edge[p] = make_int2(s, __float_as_int(nrm));
}

// ---------------- prep: weights transposed + split --------------------------
__global__ void k_wconv(const float* __restrict__ W0, const float* __restrict__ W1,
                        const float* __restrict__ W2) {
    int i = blockIdx.x * blockDim.x + threadIdx.x;
    if (i >= 3 * HDIM * HDIM) return;
    int l = i / (HDIM * HDIM);
    int r = i % (HDIM * HDIM);
    int nn = r / HDIM, kk = r % HDIM;
    const float* W = (l == 0) ? W0 : (l == 1) ? W1 : W2;
    float v = W[kk * HDIM + nn];
    __nv_bfloat16 hi, lo;
    split_bf16(v, hi, lo);
    g_Wth[l * HDIM * HDIM + nn * HDIM + kk] = hi;
    g_Wtl[l * HDIM * HDIM + nn * HDIM + kk] = lo;
}

// ---------------- GEMM: Hb = A @ W + b via mma.sync -------------------------
// A from fp32 X0 (layer 0, converted in-register) or bf16 g_xb (layers 1,2).
#define PADB 272
#define SM_A  0
#define SM_BH (128 * PADB)
#define SM_BL (2 * 128 * PADB)
#define SM_TOT (3 * 128 * PADB)

__global__ __launch_bounds__(256, 2) void k_gemm_mma(
    const float* __restrict__ X0,
    const __nv_bfloat16* __restrict__ Wh,
    const __nv_bfloat16* __restrict__ Wl,
    const float* __restrict__ bias,
    int n)
{
    extern __shared__ __align__(16) char smem[];
    uint32_t sb = smem_to_u32(smem);
    int tid = threadIdx.x;
    int lane = tid & 31, wid = tid >> 5;
    int wr = wid & 3;
    int wc = wid >> 2;
    int blockRow = blockIdx.x * 128;

    // B fill (always) + A fill (two sources)
    #pragma unroll
    for (int i = 0; i < 8; i++) {
        int gi = tid + i * 256;
        int r = gi >> 4, c16 = gi & 15;
        *(uint4*)(smem + SM_BH + r * PADB + c16 * 16) =
            *(const uint4*)&Wh[(size_t)r * HDIM + c16 * 8];
        *(uint4*)(smem + SM_BL + r * PADB + c16 * 16) =
            *(const uint4*)&Wl[(size_t)r * HDIM + c16 * 8];
    }
    if (X0 != nullptr) {
        // layer 0: read fp32 x, convert to bf16 in registers
        #pragma unroll
        for (int i = 0; i < 8; i++) {
            int gi = tid + i * 256;
            int r = gi >> 4, c8 = (gi & 15) << 3;
            int row = blockRow + r;
            uint4 va = make_uint4(0, 0, 0, 0);
            if (row < n) {
                float4 v0 = *(const float4*)&X0[(size_t)row * HDIM + c8];
                float4 v1 = *(const float4*)&X0[(size_t)row * HDIM + c8 + 4];
                __nv_bfloat162 a, b, c, d;
                a.x = __float2bfloat16_rn(v0.x); a.y = __float2bfloat16_rn(v0.y);
                b.x = __float2bfloat16_rn(v0.z); b.y = __float2bfloat16_rn(v0.w);
                c.x = __float2bfloat16_rn(v1.x); c.y = __float2bfloat16_rn(v1.y);
                d.x = __float2bfloat16_rn(v1.z); d.y = __float2bfloat16_rn(v1.w);
                va.x = *(uint32_t*)&a; va.y = *(uint32_t*)&b;
                va.z = *(uint32_t*)&c; va.w = *(uint32_t*)&d;
            }
            *(uint4*)(smem + SM_A + r * PADB + c8 * 2) = va;
        }
    } else {
        #pragma unroll
        for (int i = 0; i < 8; i++) {
            int gi = tid + i * 256;
            int r = gi >> 4, c16 = gi & 15;
            int row = blockRow + r;
            uint4 va = make_uint4(0, 0, 0, 0);
            if (row < n) va = *(const uint4*)&g_xb[(size_t)row * HDIM + c16 * 8];
            *(uint4*)(smem + SM_A + r * PADB + c16 * 16) = va;
        }
    }
    __syncthreads();

    float c[2][8][4];
    #pragma unroll
    for (int mt = 0; mt < 2; mt++)
        #pragma unroll
        for (int nt = 0; nt < 8; nt++)
            #pragma unroll
            for (int j = 0; j < 4; j++) c[mt][nt][j] = 0.0f;

    int q = lane >> 3, rl = lane & 7;
    int rowA = wr * 32 + (q & 1) * 8 + rl;
    int colA = (q >> 1) * 16;
    int rowB = wc * 64 + (q >> 1) * 8 + rl;
    int colB = (q & 1) * 16;

    #pragma unroll
    for (int ks = 0; ks < 8; ks++) {
        uint32_t a[2][4];
        #pragma unroll
        for (int mt = 0; mt < 2; mt++)
            ldsm_x4(sb + SM_A + (rowA + mt * 16) * PADB + ks * 32 + colA,
                    a[mt][0], a[mt][1], a[mt][2], a[mt][3]);

        #pragma unroll
        for (int pass = 0; pass < 2; pass++) {
            uint32_t base = pass ? SM_BL : SM_BH;
            uint32_t b[8][2];
            #pragma unroll
            for (int pr = 0; pr < 4; pr++)
                ldsm_x4(sb + base + (rowB + pr * 16) * PADB + ks * 32 + colB,
                        b[2 * pr][0], b[2 * pr][1], b[2 * pr + 1][0], b[2 * pr + 1][1]);
            #pragma unroll
            for (int mt = 0; mt < 2; mt++)
                #pragma unroll
                for (int nt = 0; nt < 8; nt++)
                    mma_bf16(c[mt][nt], a[mt][0], a[mt][1], a[mt][2], a[mt][3],
                             b[nt][0], b[nt][1]);
        }
    }

    int g = lane >> 2, t = lane & 3;
    #pragma unroll
    for (int nt = 0; nt < 8; nt++) {
        int col = wc * 64 + nt * 8 + 2 * t;
        float2 bv = *(const float2*)&bias[col];
        #pragma unroll
        for (int mt = 0; mt < 2; mt++) {
            int row0 = blockRow + wr * 32 + mt * 16 + g;
            if (row0 < n) {
                __nv_bfloat162 p;
                p.x = __float2bfloat16_rn(c[mt][nt][0] + bv.x);
                p.y = __float2bfloat16_rn(c[mt][nt][1] + bv.y);
                *(__nv_bfloat162*)&g_hb[(size_t)row0 * HDIM + col] = p;
            }
            if (row0 + 8 < n) {
                __nv_bfloat162 p;
                p.x = __float2bfloat16_rn(c[mt][nt][2] + bv.x);
                p.y = __float2bfloat16_rn(c[mt][nt][3] + bv.y);
                *(__nv_bfloat162*)&g_hb[(size_t)(row0 + 8) * HDIM + col] = p;
            }
        }
    }
}

// ---------------- aggregation: half-warp per node, packed edges, 4-wide -----
__global__ __launch_bounds__(256) void k_aggregate(int n) {
    int node = (blockIdx.x * blockDim.x + threadIdx.x) >> 4;
    int hl = threadIdx.x & 15;
    if (node >= n) return;
    int cbase = hl * 8;

    int beg = g_rowptr[node], end = g_rowptr[node + 1];
    float invd = 1.0f / (float)(end - beg + 1);

    float a[8];
    {
        uint4 us = *(const uint4*)&g_hb[(size_t)node * HDIM + cbase];
        float2 t;
        t = __bfloat1622float2(*(__nv_bfloat162*)&us.x); a[0] = t.x * invd; a[1] = t.y * invd;
        t = __bfloat1622float2(*(__nv_bfloat162*)&us.y); a[2] = t.x * invd; a[3] = t.y * invd;
        t = __bfloat1622float2(*(__nv_bfloat162*)&us.z); a[4] = t.x * invd; a[5] = t.y * invd;
        t = __bfloat1622float2(*(__nv_bfloat162*)&us.w); a[6] = t.x * invd; a[7] = t.y * invd;
    }

    int p = beg;
    for (; p + 3 < end; p += 4) {
        int2 e0 = g_edge[p],     e1 = g_edge[p + 1];
        int2 e2 = g_edge[p + 2], e3 = g_edge[p + 3];
        uint4 u0 = *(const uint4*)&g_hb[(size_t)e0.x * HDIM + cbase];
        uint4 u1 = *(const uint4*)&g_hb[(size_t)e1.x * HDIM + cbase];
        uint4 u2 = *(const uint4*)&g_hb[(size_t)e2.x * HDIM + cbase];
        uint4 u3 = *(const uint4*)&g_hb[(size_t)e3.x * HDIM + cbase];
        acc8(a, u0, __int_as_float(e0.y));
        acc8(a, u1, __int_as_float(e1.y));
        acc8(a, u2, __int_as_float(e2.y));
        acc8(a, u3, __int_as_float(e3.y));
    }
    for (; p < end; p++) {
        int2 e0 = g_edge[p];
        uint4 u = *(const uint4*)&g_hb[(size_t)e0.x * HDIM + cbase];
        acc8(a, u, __int_as_float(e0.y));
    }

    #pragma unroll
    for (int j = 0; j < 8; j++) a[j] = fmaxf(a[j], 0.0f);

    __nv_bfloat162 p0, p1, p2, p3;
    p0.x = __float2bfloat16_rn(a[0]); p0.y = __float2bfloat16_rn(a[1]);
    p1.x = __float2bfloat16_rn(a[2]); p1.y = __float2bfloat16_rn(a[3]);
    p2.x = __float2bfloat16_rn(a[4]); p2.y = __float2bfloat16_rn(a[5]);
    p3.x = __float2bfloat16_rn(a[6]); p3.y = __float2bfloat16_rn(a[7]);
    uint4 pk;
    pk.x = *(uint32_t*)&p0; pk.y = *(uint32_t*)&p1;
    pk.z = *(uint32_t*)&p2; pk.w = *(uint32_t*)&p3;
    *(uint4*)&g_xb[(size_t)node * HDIM + cbase] = pk;
}

// ---------------- segment-mean pool (bf16 input) + 2-layer MLP head ---------
__device__ __forceinline__ int lbound(const int* __restrict__ a, int n, int key) {
    int lo = 0, hi = n;
    while (lo < hi) { int m = (lo + hi) >> 1; if (a[m] < key) lo = m + 1; else hi = m; }
    return lo;
}

__global__ __launch_bounds__(128) void k_pool_mlp(const int* __restrict__ batch, int n,
                                                  const float* __restrict__ Wp1,
                                                  const float* __restrict__ bp1,
                                                  const float* __restrict__ Wp2,
                                                  const float* __restrict__ bp2,
                                                  float* __restrict__ out) {
    int g = blockIdx.x;
    int t = threadIdx.x;
    int beg = lbound(batch, n, g);
    int end = lbound(batch, n, g + 1);
    float s = 0.0f;
    for (int r = beg; r < end; r++)
        s += __bfloat162float(g_xb[(size_t)r * HDIM + t]);
    float cnt = (float)(end - beg);
    float inv = 1.0f / fmaxf(cnt, 1.0f);

    __shared__ float ps[HDIM];
    ps[t] = s * inv;
    __syncthreads();

    float hid = bp1[t];
    #pragma unroll
    for (int k = 0; k < HDIM; k++) hid += ps[k] * Wp1[k * HDIM + t];
    hid = fmaxf(hid, 0.0f);

    float term = hid * Wp2[t];
    #pragma unroll
    for (int o = 16; o > 0; o >>= 1) term += __shfl_down_sync(0xFFFFFFFFu, term, o);
    __shared__ float rs[4];
    int lane = t & 31, wid = t >> 5;
    if (lane == 0) rs[wid] = term;
    __syncthreads();
    if (t == 0) out[g] = rs[0] + rs[1] + rs[2] + rs[3] + bp2[0];
}

// ---------------- launch -----------------------------------------------------
extern "C" void kernel_launch(void* const* d_in, const int* in_sizes, int n_in,
                              void* d_out, int out_size) {
    const float* x     = (const float*)d_in[0];
    const int*   ei    = (const int*)d_in[1];
    const int*   batch = (const int*)d_in[2];
    const float* Ws[3] = {(const float*)d_in[3], (const float*)d_in[5], (const float*)d_in[7]};
    const float* bs[3] = {(const float*)d_in[4], (const float*)d_in[6], (const float*)d_in[8]};
    const float* Wp1 = (const float*)d_in[9];
    const float* bp1 = (const float*)d_in[10];
    const float* Wp2 = (const float*)d_in[11];
    const float* bp2 = (const float*)d_in[12];
    float* out = (float*)d_out;

    int n = in_sizes[0] / HDIM;
    int e = in_sizes[1] / 2;
    const int* src = ei;
    const int* dst = ei + e;

    int nb_n = (n + 255) / 256;
    int nb_e = (e + 255) / 256;
    int nscan = (n + 1023) / 1024;

    cudaFuncSetAttribute(k_gemm_mma, cudaFuncAttributeMaxDynamicSharedMemorySize, SM_TOT);

    __nv_bfloat16* Wh0; cudaGetSymbolAddress((void**)&Wh0, g_Wth);
    __nv_bfloat16* Wl0; cudaGetSymbolAddress((void**)&Wl0, g_Wtl);

    // CSR build (single stream, serial — R10 proved concurrency contends)
    k_init<<<nb_n, 256>>>(n);
    k_count<<<nb_e, 256>>>(dst, e);
    k_scan1<<<nscan, 1024>>>(n);
    k_scan2<<<1, 128>>>(nscan);
    k_scan3<<<nb_n, 256>>>(n, e);
    k_fill<<<nb_e, 256>>>(src, dst, e);

    // weight split (transposed bf16 hi/lo)
    k_wconv<<<(3 * HDIM * HDIM + 255) / 256, 256>>>(Ws[0], Ws[1], Ws[2]);

    int gemm_blocks = (n + 127) / 128;
    int agg_blocks = (n + 15) / 16;

    // layer 0: fp32 x converted inside the A-fill
    k_gemm_mma<<<gemm_blocks, 256, SM_TOT>>>(x, Wh0, Wl0, bs[0], n);
    k_aggregate<<<agg_blocks, 256>>>(n);
    // layers 1,2: bf16 g_xb input
    k_gemm_mma<<<gemm_blocks, 256, SM_TOT>>>(nullptr, Wh0 + HDIM * HDIM,
                                             Wl0 + HDIM * HDIM, bs[1], n);
    k_aggregate<<<agg_blocks, 256>>>(n);
    k_gemm_mma<<<gemm_blocks, 256, SM_TOT>>>(nullptr, Wh0 + 2 * HDIM * HDIM,
                                             Wl0 + 2 * HDIM * HDIM, bs[2], n);
    k_aggregate<<<agg_blocks, 256>>>(n);

    // pool + MLP head
    k_pool_mlp<<<out_size, 128>>>(batch, n, Wp1, bp1, Wp2, bp2, out);
}